// round 1
// baseline (speedup 1.0000x reference)
#include <cuda_runtime.h>
#include <math.h>

// Scalar accumulator + nothing else: scratch lives in __device__ globals
// (allocation inside kernel_launch is forbidden).
__device__ double g_sum;

__global__ void ssim_init_kernel() {
    g_sum = 0.0;
}

__global__ __launch_bounds__(256) void ssim_reduce_kernel(
    const float4* __restrict__ pred,
    const float4* __restrict__ target,
    int n_rows)
{
    const float DELTA = 0.1f;
    const float INV3  = 1.0f / 3.0f;   // 1/(D-1), D=4

    float local = 0.0f;

    int stride = gridDim.x * blockDim.x;
    for (int i = blockIdx.x * blockDim.x + threadIdx.x; i < n_rows; i += stride) {
        float4 p = pred[i];
        float4 t = target[i];

        float sp = (p.x + p.y) + (p.z + p.w);
        float st = (t.x + t.y) + (t.z + t.w);
        float mp = sp * 0.25f;
        float mt = st * 0.25f;

        float dpx = p.x - mp, dpy = p.y - mp, dpz = p.z - mp, dpw = p.w - mp;
        float dtx = t.x - mt, dty = t.y - mt, dtz = t.z - mt, dtw = t.w - mt;

        float vp  = (dpx*dpx + dpy*dpy + dpz*dpz + dpw*dpw) * INV3;
        float vt  = (dtx*dtx + dty*dty + dtz*dtz + dtw*dtw) * INV3;
        float cov = (dpx*dtx + dpy*dty + dpz*dtz + dpw*dtw) * INV3;

        float a1 = 2.0f * mp * mt + DELTA;
        float a2 = 2.0f * cov + DELTA;
        float b1 = mp * mp + mt * mt + DELTA;
        float b2 = vp + vt + DELTA;

        float similar = (a1 * a2) / (b1 * b2 + DELTA);
        local += 1.0f - similar;
    }

    // Warp reduce
    #pragma unroll
    for (int off = 16; off > 0; off >>= 1)
        local += __shfl_down_sync(0xFFFFFFFFu, local, off);

    // Block reduce across warps
    __shared__ float warp_sums[8];   // 256 threads = 8 warps
    int lane = threadIdx.x & 31;
    int wid  = threadIdx.x >> 5;
    if (lane == 0) warp_sums[wid] = local;
    __syncthreads();

    if (wid == 0) {
        float v = (lane < 8) ? warp_sums[lane] : 0.0f;
        #pragma unroll
        for (int off = 4; off > 0; off >>= 1)
            v += __shfl_down_sync(0xFFFFFFFFu, v, off);
        if (lane == 0)
            atomicAdd(&g_sum, (double)v);
    }
}

__global__ void ssim_finalize_kernel(float* __restrict__ out, int n_rows) {
    double s = g_sum;
    float r = (float)(s / (double)n_rows);
    // Reference NaN fallback: sum(ones)/n_elem == 1.0. Any NaN in the inputs
    // propagates through IEEE arithmetic into the sum, so isnan(r) covers both
    // the "loss is NaN" and "inputs contain NaN" branches.
    out[0] = isnan(r) ? 1.0f : r;
}

extern "C" void kernel_launch(void* const* d_in, const int* in_sizes, int n_in,
                              void* d_out, int out_size)
{
    const float4* pred   = (const float4*)d_in[0];
    const float4* target = (const float4*)d_in[1];
    float* out = (float*)d_out;

    int n_rows = in_sizes[0] / 4;   // [N, 4] float32 -> N float4 rows

    ssim_init_kernel<<<1, 1>>>();

    const int threads = 256;
    const int blocks  = 1184;       // 148 SMs * 8 blocks
    ssim_reduce_kernel<<<blocks, threads>>>(pred, target, n_rows);

    ssim_finalize_kernel<<<1, 1>>>(out, n_rows);
}

// round 2
// speedup vs baseline: 1.0920x; 1.0920x over previous
#include <cuda_runtime.h>
#include <math.h>

// Scratch in __device__ globals (allocation anywhere is forbidden).
// Zero-initialized at module load; the last block resets them each run,
// so graph replays are deterministic.
__device__ double g_sum;
__device__ unsigned int g_count;

__device__ __forceinline__ float rcp_approx(float x) {
    float r;
    asm("rcp.approx.f32 %0, %1;" : "=f"(r) : "f"(x));
    return r;
}

struct RowVals { float num; float den; };

__device__ __forceinline__ RowVals row_terms(float4 p, float4 t) {
    const float DELTA = 0.1f;
    const float INV3  = 1.0f / 3.0f;

    float mp = ((p.x + p.y) + (p.z + p.w)) * 0.25f;
    float mt = ((t.x + t.y) + (t.z + t.w)) * 0.25f;

    float dpx = p.x - mp, dpy = p.y - mp, dpz = p.z - mp, dpw = p.w - mp;
    float dtx = t.x - mt, dty = t.y - mt, dtz = t.z - mt, dtw = t.w - mt;

    float vp  = (dpx*dpx + dpy*dpy + dpz*dpz + dpw*dpw) * INV3;
    float vt  = (dtx*dtx + dty*dty + dtz*dtz + dtw*dtw) * INV3;
    float cov = (dpx*dtx + dpy*dty + dpz*dtz + dpw*dtw) * INV3;

    float a1 = 2.0f * mp * mt + DELTA;
    float a2 = 2.0f * cov + DELTA;
    float b1 = mp * mp + mt * mt + DELTA;
    float b2 = vp + vt + DELTA;

    RowVals r;
    r.num = a1 * a2;
    r.den = b1 * b2 + DELTA;   // >= 0.11 for finite inputs
    return r;
}

__global__ __launch_bounds__(256) void ssim_fused_kernel(
    const float4* __restrict__ pred,
    const float4* __restrict__ target,
    int n_rows,
    float* __restrict__ out)
{
    const int T   = gridDim.x * blockDim.x;
    const int tid = blockIdx.x * blockDim.x + threadIdx.x;

    float local = 0.0f;
    int i = tid;

    // Main loop: 4 rows per iteration at stride T (each LDG.128 fully
    // coalesced), one MUFU.RCP per 4 rows via batched reciprocal.
    for (; i + 3 * T < n_rows; i += 4 * T) {
        float4 p0 = pred[i];         float4 t0 = target[i];
        float4 p1 = pred[i + T];     float4 t1 = target[i + T];
        float4 p2 = pred[i + 2*T];   float4 t2 = target[i + 2*T];
        float4 p3 = pred[i + 3*T];   float4 t3 = target[i + 3*T];

        RowVals r0 = row_terms(p0, t0);
        RowVals r1 = row_terms(p1, t1);
        RowVals r2 = row_terms(p2, t2);
        RowVals r3 = row_terms(p3, t3);

        // Montgomery batched reciprocal: one rcp for all 4 denominators.
        float p01   = r0.den * r1.den;
        float p012  = p01 * r2.den;
        float prod  = p012 * r3.den;

        float rinv = rcp_approx(prod);
        // One Newton step: rinv = rinv * (2 - prod*rinv)
        rinv = rinv * __fmaf_rn(-prod, rinv, 2.0f);

        float s23  = r2.den * r3.den;
        float inv0 = rinv * (r1.den * s23);
        float inv1 = (rinv * r0.den) * s23;
        float inv2 = (rinv * p01) * r3.den;
        float inv3 = rinv * p012;

        float sim = r0.num * inv0 + r1.num * inv1
                  + r2.num * inv2 + r3.num * inv3;
        local += 4.0f - sim;
    }

    // Tail: remaining rows one at a time (<= 3 per thread).
    for (; i < n_rows; i += T) {
        RowVals r = row_terms(pred[i], target[i]);
        float rinv = rcp_approx(r.den);
        rinv = rinv * __fmaf_rn(-r.den, rinv, 2.0f);
        local += 1.0f - r.num * rinv;
    }

    // Warp reduce
    #pragma unroll
    for (int off = 16; off > 0; off >>= 1)
        local += __shfl_down_sync(0xFFFFFFFFu, local, off);

    __shared__ float warp_sums[8];
    int lane = threadIdx.x & 31;
    int wid  = threadIdx.x >> 5;
    if (lane == 0) warp_sums[wid] = local;
    __syncthreads();

    if (wid == 0) {
        float v = (lane < 8) ? warp_sums[lane] : 0.0f;
        #pragma unroll
        for (int off = 4; off > 0; off >>= 1)
            v += __shfl_down_sync(0xFFFFFFFFu, v, off);
        if (lane == 0)
            atomicAdd(&g_sum, (double)v);
    }

    // Last-block-done: finalize inline, reset scratch for next replay.
    if (threadIdx.x == 0) {
        __threadfence();
        unsigned int done = atomicAdd(&g_count, 1u);
        if (done == gridDim.x - 1) {
            double s = g_sum;
            float r = (float)(s / (double)n_rows);
            // NaN in any input propagates through the arithmetic into the
            // sum, so isnan(r) covers the reference's full nan_flag; the
            // fallback value sum(ones)/n_elem == 1.0.
            out[0] = isnan(r) ? 1.0f : r;
            g_sum = 0.0;
            g_count = 0u;
        }
    }
}

extern "C" void kernel_launch(void* const* d_in, const int* in_sizes, int n_in,
                              void* d_out, int out_size)
{
    const float4* pred   = (const float4*)d_in[0];
    const float4* target = (const float4*)d_in[1];
    float* out = (float*)d_out;

    int n_rows = in_sizes[0] / 4;   // [N, 4] float32 -> N float4 rows

    const int threads = 256;
    const int blocks  = 1184;       // 148 SMs * 8 blocks
    ssim_fused_kernel<<<blocks, threads>>>(pred, target, n_rows, out);
}